// round 1
// baseline (speedup 1.0000x reference)
#include <cuda_runtime.h>
#include <math.h>

#define B_    1024
#define VOCAB 32000
#define D_    128
#define KNEG  5

// ---------------- device scratch (no runtime allocation allowed) ----------------
__device__ float g_EviT[D_ * B_];     // E^T  [d][b]   (vi @ V transposed)
__device__ float g_UT[D_ * VOCAB];    // U^T  [d][v]
__device__ float g_s[B_];             // s[b] = vi_embed . vo_embed
__device__ float g_bm[B_ * KNEG];     // batch_mul[b][k]

// ---------------- kernel 0: zero accumulators ----------------
__global__ void zero_kernel() {
    int i = blockIdx.x * blockDim.x + threadIdx.x;
    if (i < D_ * B_)    g_EviT[i] = 0.f;
    if (i < B_)         g_s[i]    = 0.f;
    if (i < B_ * KNEG)  g_bm[i]   = 0.f;
}

// ---------------- kernel 0b: transpose U [VOC][D] -> g_UT [D][VOC] ----------------
__global__ void transposeU_kernel(const float* __restrict__ U) {
    __shared__ float t[32][33];
    int v0 = blockIdx.x * 32;
    int d0 = blockIdx.y * 32;
    int tx = threadIdx.x, ty = threadIdx.y;        // 32 x 8
    #pragma unroll
    for (int i = 0; i < 32; i += 8)
        t[ty + i][tx] = U[(long)(v0 + ty + i) * D_ + d0 + tx];
    __syncthreads();
    #pragma unroll
    for (int i = 0; i < 32; i += 8)
        g_UT[(long)(d0 + ty + i) * VOCAB + v0 + tx] = t[tx][ty + i];
}

// ---------------- kernel 1: E^T += (vi @ V)^T  (split-K, atomic epilogue) ----------------
// M=1024(b), N=128(d), K=32000(v). Tile: 64b x 64d, BK=32, splitK=20 (chunk 1600).
// 256 threads, 4x4 register tile per thread.
__global__ __launch_bounds__(256) void gemm_vi_V(const float* __restrict__ vi,
                                                 const float* __restrict__ V) {
    const int b0 = blockIdx.y * 64;
    const int d0 = blockIdx.z * 64;
    const int v0 = blockIdx.x * 1600;

    __shared__ float As[32][65];   // [k][b]  pad 65: conflict-free transposed writes
    __shared__ float Bs[32][64];   // [k][d]

    const int tid  = threadIdx.x;
    const int tx   = tid % 16;     // d direction  (16 * 4 = 64)
    const int ty   = tid / 16;     // b direction  (16 * 4 = 64)
    const int lane = tid % 32;
    const int wrp  = tid / 32;

    float acc[4][4] = {};

    for (int kk = 0; kk < 1600; kk += 32) {
        // A: vi[b0+row][v0+kk+lane], each warp does rows {w, w+8, ...}  (coalesced in v)
        #pragma unroll
        for (int s = 0; s < 8; s++)
            As[lane][wrp + 8 * s] = vi[(long)(b0 + wrp + 8 * s) * VOCAB + v0 + kk + lane];
        // B: V[v0+kk+r][d0+c], 64-wide coalesced rows
        {
            int c = tid % 64, r = tid / 64;   // r in 0..3
            #pragma unroll
            for (int s = 0; s < 8; s++)
                Bs[r + 4 * s][c] = V[(long)(v0 + kk + r + 4 * s) * D_ + d0 + c];
        }
        __syncthreads();
        #pragma unroll
        for (int k = 0; k < 32; k++) {
            float a[4];
            #pragma unroll
            for (int i = 0; i < 4; i++) a[i] = As[k][ty * 4 + i];   // broadcast reads
            float4 bv = *(const float4*)&Bs[k][tx * 4];
            float b[4] = {bv.x, bv.y, bv.z, bv.w};
            #pragma unroll
            for (int i = 0; i < 4; i++)
                #pragma unroll
                for (int j = 0; j < 4; j++)
                    acc[i][j] += a[i] * b[j];
        }
        __syncthreads();
    }
    #pragma unroll
    for (int i = 0; i < 4; i++)
        #pragma unroll
        for (int j = 0; j < 4; j++)
            atomicAdd(&g_EviT[(long)(d0 + tx * 4 + j) * B_ + b0 + ty * 4 + i], acc[i][j]);
}

// ---------------- kernel 2: fused W-tile GEMM + streaming consume ----------------
// Per block: W[32b x 128v] = E[32b x 128d] @ U^T[128d x 128v], then immediately
// consume with vo / neg streams; accumulate s[b], bm[b][k] via warp-reduce + atomics.
__global__ __launch_bounds__(256) void fused_loss(const float* __restrict__ vo,
                                                  const float* __restrict__ neg) {
    const int v0 = blockIdx.x * 128;
    const int b0 = blockIdx.y * 32;

    __shared__ float Es[32][32];    // [dk][b]
    __shared__ float Us[32][128];   // [dk][v]

    const int tid = threadIdx.x;
    const int tx  = tid % 32;       // v direction (32 * 4 = 128)
    const int ty  = tid / 32;       // b direction ( 8 * 4 = 32)

    float w[4][4] = {};             // [ib][jv]

    for (int dd = 0; dd < D_; dd += 32) {
        {   // Es: 1024 floats, one float4 per thread
            int b4 = tid % 8, dk = tid / 8;
            *(float4*)&Es[dk][b4 * 4] =
                *(const float4*)&g_EviT[(long)(dd + dk) * B_ + b0 + b4 * 4];
        }
        {   // Us: 4096 floats, 4 float4 per thread (coalesced rows of g_UT)
            int c4 = tid % 32, r = tid / 32;
            #pragma unroll
            for (int s = 0; s < 4; s++)
                *(float4*)&Us[r + 8 * s][c4 * 4] =
                    *(const float4*)&g_UT[(long)(dd + r + 8 * s) * VOCAB + v0 + c4 * 4];
        }
        __syncthreads();
        #pragma unroll
        for (int k = 0; k < 32; k++) {
            float4 uv = *(const float4*)&Us[k][tx * 4];
            float u[4] = {uv.x, uv.y, uv.z, uv.w};
            float a[4];
            #pragma unroll
            for (int i = 0; i < 4; i++) a[i] = Es[k][ty * 4 + i];   // broadcast
            #pragma unroll
            for (int i = 0; i < 4; i++)
                #pragma unroll
                for (int j = 0; j < 4; j++)
                    w[i][j] += a[i] * u[j];
        }
        __syncthreads();
    }

    // consume: stream vo and neg tiles (fully coalesced float4 across the warp)
    float s_loc[4];
    float bm_loc[4][KNEG];
    #pragma unroll
    for (int i = 0; i < 4; i++) {
        const long b = b0 + ty * 4 + i;
        float4 v4 = *(const float4*)&vo[b * VOCAB + v0 + tx * 4];
        s_loc[i] = v4.x * w[i][0] + v4.y * w[i][1] + v4.z * w[i][2] + v4.w * w[i][3];
        #pragma unroll
        for (int k = 0; k < KNEG; k++) {
            float4 n4 = *(const float4*)&neg[(b * KNEG + k) * VOCAB + v0 + tx * 4];
            bm_loc[i][k] = n4.x * w[i][0] + n4.y * w[i][1] + n4.z * w[i][2] + n4.w * w[i][3];
        }
    }

    // warp reduction over tx (all 32 lanes of a warp share the same ty -> same 4 b's)
    #pragma unroll
    for (int off = 16; off > 0; off >>= 1) {
        #pragma unroll
        for (int i = 0; i < 4; i++) {
            s_loc[i] += __shfl_xor_sync(0xffffffffu, s_loc[i], off);
            #pragma unroll
            for (int k = 0; k < KNEG; k++)
                bm_loc[i][k] += __shfl_xor_sync(0xffffffffu, bm_loc[i][k], off);
        }
    }
    if ((tid & 31) == 0) {
        #pragma unroll
        for (int i = 0; i < 4; i++) {
            int b = b0 + ty * 4 + i;
            atomicAdd(&g_s[b], s_loc[i]);
            #pragma unroll
            for (int k = 0; k < KNEG; k++)
                atomicAdd(&g_bm[b * KNEG + k], bm_loc[i][k]);
        }
    }
}

// ---------------- kernel 3: finalize loss ----------------
__device__ __forceinline__ float logsig(float x) {
    return fminf(x, 0.f) - log1pf(expf(-fabsf(x)));
}

__global__ void finalize_kernel(float* __restrict__ out) {
    __shared__ float red[B_];
    int b = threadIdx.x;
    float left  = logsig(g_s[b]);
    float right = 0.f;
    #pragma unroll
    for (int k = 0; k < KNEG; k++)
        right += logsig(-g_bm[b * KNEG + k]);
    red[b] = -(left + right);
    __syncthreads();
    for (int off = B_ / 2; off > 0; off >>= 1) {
        if (b < off) red[b] += red[b + off];
        __syncthreads();
    }
    if (b == 0) out[0] = red[0] / (float)B_;
}

// ---------------- launch ----------------
extern "C" void kernel_launch(void* const* d_in, const int* in_sizes, int n_in,
                              void* d_out, int out_size) {
    const float* vi  = (const float*)d_in[0];   // [B, VOC]
    const float* vo  = (const float*)d_in[1];   // [B, VOC]
    const float* neg = (const float*)d_in[2];   // [B, K, VOC]
    const float* V   = (const float*)d_in[3];   // [VOC, D]
    const float* U   = (const float*)d_in[4];   // [VOC, D]
    float* out = (float*)d_out;

    zero_kernel<<<(D_ * B_ + 255) / 256, 256>>>();
    transposeU_kernel<<<dim3(VOCAB / 32, D_ / 32), dim3(32, 8)>>>(U);
    gemm_vi_V<<<dim3(20, B_ / 64, D_ / 64), 256>>>(vi, V);       // splitK=20
    fused_loss<<<dim3(VOCAB / 128, B_ / 32), 256>>>(vo, neg);
    finalize_kernel<<<1, B_>>>(out);
}

// round 3
// speedup vs baseline: 1.7901x; 1.7901x over previous
#include <cuda_runtime.h>
#include <math.h>
#include <stdint.h>

#define B_    1024
#define VOCAB 32000
#define D_    128
#define KNEG  5

// ---------------- device scratch ----------------
__device__ float g_E[B_ * D_];       // vi @ V   [b][d]  (fp32 accum)
__device__ float g_s[B_];
__device__ float g_bm[B_ * KNEG];

// ---------------- helpers ----------------
__device__ __forceinline__ uint32_t to_tf32(float f) {
    uint32_t u;
    asm("cvt.rna.tf32.f32 %0, %1;" : "=r"(u) : "f"(f));
    return u;
}

// m16n8k8 tf32 mma, row.col, fp32 accumulate (legal PTX for compute_103)
__device__ __forceinline__ void mma8(float c[4], const uint32_t a[4], const uint32_t b[2]) {
    asm volatile(
        "mma.sync.aligned.m16n8k8.row.col.f32.tf32.tf32.f32 "
        "{%0,%1,%2,%3}, {%4,%5,%6,%7}, {%8,%9}, {%0,%1,%2,%3};"
        : "+f"(c[0]), "+f"(c[1]), "+f"(c[2]), "+f"(c[3])
        : "r"(a[0]), "r"(a[1]), "r"(a[2]), "r"(a[3]), "r"(b[0]), "r"(b[1]));
}

// ---------------- kernel 0: zero accumulators ----------------
__global__ void zero_kernel() {
    int i = blockIdx.x * blockDim.x + threadIdx.x;
    if (i < B_ * D_)   g_E[i]  = 0.f;
    if (i < B_)        g_s[i]  = 0.f;
    if (i < B_ * KNEG) g_bm[i] = 0.f;
}

// ---------------- kernel 1: E += vi @ V  (mma.sync tf32, split-K) ----------------
// M=1024(b) N=128(d) K=32000(v). grid (20 k-chunks, 8 m-tiles); chunk=1600, BK=32.
// 8 warps: 4(m) x 2(n), warp tile 32x64.
#define APITCH 36
#define BPITCH 132
__global__ __launch_bounds__(256, 2) void gemm1(const float* __restrict__ vi,
                                                const float* __restrict__ V) {
    __shared__ uint32_t As[128 * APITCH];   // [m][k]  tf32 bits
    __shared__ uint32_t Bs[32 * BPITCH];    // [k][n]  tf32 bits

    const int tid = threadIdx.x, wid = tid >> 5, lane = tid & 31;
    const int g = lane >> 2, t = lane & 3;
    const int wm = wid >> 1, wn = wid & 1;
    const int b0 = blockIdx.y * 128;
    const int vbase = blockIdx.x * 1600;

    float c[2][8][4] = {};

    for (int it = 0; it < 50; it++) {
        const int kk = vbase + it * 32;
        __syncthreads();
        // As: 128 rows x 32 k  (8 float4 per row)
        #pragma unroll
        for (int s = 0; s < 4; s++) {
            int idx = tid + s * 256;
            int row = idx >> 3, c4 = idx & 7;
            float4 v = *(const float4*)(vi + (size_t)(b0 + row) * VOCAB + kk + c4 * 4);
            uint32_t* p = &As[row * APITCH + c4 * 4];
            p[0] = to_tf32(v.x); p[1] = to_tf32(v.y); p[2] = to_tf32(v.z); p[3] = to_tf32(v.w);
        }
        // Bs: 32 k-rows x 128 d  (V rows are contiguous 512B)
        #pragma unroll
        for (int s = 0; s < 4; s++) {
            int idx = tid + s * 256;
            int k = idx >> 5, c4 = idx & 31;
            float4 v = *(const float4*)(V + (size_t)(kk + k) * D_ + c4 * 4);
            uint32_t* p = &Bs[k * BPITCH + c4 * 4];
            p[0] = to_tf32(v.x); p[1] = to_tf32(v.y); p[2] = to_tf32(v.z); p[3] = to_tf32(v.w);
        }
        __syncthreads();
        #pragma unroll
        for (int k8 = 0; k8 < 4; k8++) {
            const int kb = k8 * 8;
            uint32_t a[2][4];
            #pragma unroll
            for (int i = 0; i < 2; i++) {
                int m = wm * 32 + i * 16;
                a[i][0] = As[(m + g) * APITCH + kb + t];
                a[i][1] = As[(m + g + 8) * APITCH + kb + t];
                a[i][2] = As[(m + g) * APITCH + kb + t + 4];
                a[i][3] = As[(m + g + 8) * APITCH + kb + t + 4];
            }
            uint32_t b[8][2];
            #pragma unroll
            for (int j = 0; j < 8; j++) {
                int n = wn * 64 + j * 8 + g;
                b[j][0] = Bs[(kb + t) * BPITCH + n];
                b[j][1] = Bs[(kb + t + 4) * BPITCH + n];
            }
            #pragma unroll
            for (int i = 0; i < 2; i++)
                #pragma unroll
                for (int j = 0; j < 8; j++)
                    mma8(c[i][j], a[i], b[j]);
        }
    }
    // atomic fp32 epilogue
    #pragma unroll
    for (int i = 0; i < 2; i++) {
        #pragma unroll
        for (int j = 0; j < 8; j++) {
            int m = b0 + wm * 32 + i * 16;
            int col = wn * 64 + j * 8 + 2 * t;
            atomicAdd(&g_E[(size_t)(m + g) * D_ + col],     c[i][j][0]);
            atomicAdd(&g_E[(size_t)(m + g) * D_ + col + 1], c[i][j][1]);
            atomicAdd(&g_E[(size_t)(m + g + 8) * D_ + col],     c[i][j][2]);
            atomicAdd(&g_E[(size_t)(m + g + 8) * D_ + col + 1], c[i][j][3]);
        }
    }
}

// ---------------- kernel 2: fused W = E @ U^T tile + streaming consume ----------------
// grid (250 v-tiles, 8 b-tiles). W[128b x 128v] per CTA; then consume vo/neg streams.
#define WPITCH 132
#define F2_AS_OFF 0
#define F2_BS_OFF (128 * APITCH * 4)
#define F2_WS_OFF (2 * 128 * APITCH * 4)
#define SMEM2 (F2_WS_OFF + 128 * WPITCH * 4)
__global__ __launch_bounds__(256, 2) void fused2(const float* __restrict__ vo,
                                                 const float* __restrict__ neg,
                                                 const float* __restrict__ U) {
    extern __shared__ char smem[];
    uint32_t* As = (uint32_t*)(smem + F2_AS_OFF);   // E chunk [b][k]   128 x 32
    uint32_t* Bs = (uint32_t*)(smem + F2_BS_OFF);   // U chunk [n=v][k] 128 x 32
    float*    Ws = (float*)(smem + F2_WS_OFF);      // W tile  [b][v]   128 x 128 (pitch 132)

    const int tid = threadIdx.x, wid = tid >> 5, lane = tid & 31;
    const int g = lane >> 2, t = lane & 3;
    const int wm = wid >> 1, wn = wid & 1;
    const int v0 = blockIdx.x * 128;
    const int b0 = blockIdx.y * 128;

    float c[2][8][4] = {};

    #pragma unroll
    for (int it = 0; it < 4; it++) {
        const int kk = it * 32;
        __syncthreads();
        #pragma unroll
        for (int s = 0; s < 4; s++) {
            int idx = tid + s * 256;
            int row = idx >> 3, c4 = idx & 7;
            float4 v = *(const float4*)(g_E + (size_t)(b0 + row) * D_ + kk + c4 * 4);
            uint32_t* p = &As[row * APITCH + c4 * 4];
            p[0] = to_tf32(v.x); p[1] = to_tf32(v.y); p[2] = to_tf32(v.z); p[3] = to_tf32(v.w);
        }
        #pragma unroll
        for (int s = 0; s < 4; s++) {
            int idx = tid + s * 256;
            int row = idx >> 3, c4 = idx & 7;
            float4 v = *(const float4*)(U + (size_t)(v0 + row) * D_ + kk + c4 * 4);
            uint32_t* p = &Bs[row * APITCH + c4 * 4];
            p[0] = to_tf32(v.x); p[1] = to_tf32(v.y); p[2] = to_tf32(v.z); p[3] = to_tf32(v.w);
        }
        __syncthreads();
        #pragma unroll
        for (int k8 = 0; k8 < 4; k8++) {
            const int kb = k8 * 8;
            uint32_t a[2][4];
            #pragma unroll
            for (int i = 0; i < 2; i++) {
                int m = wm * 32 + i * 16;
                a[i][0] = As[(m + g) * APITCH + kb + t];
                a[i][1] = As[(m + g + 8) * APITCH + kb + t];
                a[i][2] = As[(m + g) * APITCH + kb + t + 4];
                a[i][3] = As[(m + g + 8) * APITCH + kb + t + 4];
            }
            uint32_t b[8][2];
            #pragma unroll
            for (int j = 0; j < 8; j++) {
                int n = wn * 64 + j * 8 + g;    // Bs is [n][k]
                b[j][0] = Bs[n * APITCH + kb + t];
                b[j][1] = Bs[n * APITCH + kb + t + 4];
            }
            #pragma unroll
            for (int i = 0; i < 2; i++)
                #pragma unroll
                for (int j = 0; j < 8; j++)
                    mma8(c[i][j], a[i], b[j]);
        }
    }
    // W fragments -> smem
    #pragma unroll
    for (int i = 0; i < 2; i++) {
        #pragma unroll
        for (int j = 0; j < 8; j++) {
            int m = wm * 32 + i * 16;
            int col = wn * 64 + j * 8 + 2 * t;
            Ws[(m + g) * WPITCH + col]     = c[i][j][0];
            Ws[(m + g) * WPITCH + col + 1] = c[i][j][1];
            Ws[(m + g + 8) * WPITCH + col]     = c[i][j][2];
            Ws[(m + g + 8) * WPITCH + col + 1] = c[i][j][3];
        }
    }
    __syncthreads();

    // consume: warp lanes span v (tx*4..tx*4+3); each warp owns 4 b-rows per pass
    const int tx = tid & 31, ty = tid >> 5;
    for (int pass = 0; pass < 4; pass++) {
        float sl[4];
        float bl[4][KNEG];
        #pragma unroll
        for (int i = 0; i < 4; i++) {
            const int brow = pass * 32 + ty * 4 + i;
            const size_t b = (size_t)(b0 + brow);
            float4 w4 = *(const float4*)&Ws[brow * WPITCH + tx * 4];
            float4 v4 = *(const float4*)(vo + b * VOCAB + v0 + tx * 4);
            sl[i] = v4.x * w4.x + v4.y * w4.y + v4.z * w4.z + v4.w * w4.w;
            #pragma unroll
            for (int k = 0; k < KNEG; k++) {
                float4 n4 = *(const float4*)(neg + (b * KNEG + k) * VOCAB + v0 + tx * 4);
                bl[i][k] = n4.x * w4.x + n4.y * w4.y + n4.z * w4.z + n4.w * w4.w;
            }
        }
        #pragma unroll
        for (int off = 16; off; off >>= 1) {
            #pragma unroll
            for (int i = 0; i < 4; i++) {
                sl[i] += __shfl_xor_sync(0xffffffffu, sl[i], off);
                #pragma unroll
                for (int k = 0; k < KNEG; k++)
                    bl[i][k] += __shfl_xor_sync(0xffffffffu, bl[i][k], off);
            }
        }
        if (tx == 0) {
            #pragma unroll
            for (int i = 0; i < 4; i++) {
                int b = b0 + pass * 32 + ty * 4 + i;
                atomicAdd(&g_s[b], sl[i]);
                #pragma unroll
                for (int k = 0; k < KNEG; k++)
                    atomicAdd(&g_bm[b * KNEG + k], bl[i][k]);
            }
        }
    }
}

// ---------------- kernel 3: finalize loss ----------------
__device__ __forceinline__ float logsig(float x) {
    return fminf(x, 0.f) - log1pf(expf(-fabsf(x)));
}

__global__ void finalize_kernel(float* __restrict__ out) {
    __shared__ float red[B_];
    int b = threadIdx.x;
    float left  = logsig(g_s[b]);
    float right = 0.f;
    #pragma unroll
    for (int k = 0; k < KNEG; k++)
        right += logsig(-g_bm[b * KNEG + k]);
    red[b] = -(left + right);
    __syncthreads();
    for (int off = B_ / 2; off > 0; off >>= 1) {
        if (b < off) red[b] += red[b + off];
        __syncthreads();
    }
    if (b == 0) out[0] = red[0] / (float)B_;
}

// ---------------- launch ----------------
extern "C" void kernel_launch(void* const* d_in, const int* in_sizes, int n_in,
                              void* d_out, int out_size) {
    const float* vi  = (const float*)d_in[0];   // [B, VOC]
    const float* vo  = (const float*)d_in[1];   // [B, VOC]
    const float* neg = (const float*)d_in[2];   // [B, K, VOC]
    const float* V   = (const float*)d_in[3];   // [VOC, D]
    const float* U   = (const float*)d_in[4];   // [VOC, D]
    float* out = (float*)d_out;

    cudaFuncSetAttribute(fused2, cudaFuncAttributeMaxDynamicSharedMemorySize, SMEM2);

    zero_kernel<<<512, 256>>>();
    gemm1<<<dim3(20, 8), 256>>>(vi, V);
    fused2<<<dim3(250, 8), 256, SMEM2>>>(vo, neg, U);
    finalize_kernel<<<1, B_>>>(out);
}